// round 14
// baseline (speedup 1.0000x reference)
#include <cuda_runtime.h>
#include <cuda_bf16.h>

// bf16 staging copy of feats (64 MB; fits entirely in the 126 MB L2).
__device__ __nv_bfloat16 g_bf[33554432];
// Per-CTA partial sums + completion counter.
__device__ float g_block[65536];
__device__ unsigned int g_count = 0;

__device__ __forceinline__ float warp_sum(float v) {
    #pragma unroll
    for (int off = 16; off > 0; off >>= 1)
        v += __shfl_down_sync(0xFFFFFFFFu, v, off);
    return v;
}

__device__ __forceinline__ uint2 pack_bf(float4 v) {
    __nv_bfloat162 lo = __floats2bfloat162_rn(v.x, v.y);
    __nv_bfloat162 hi = __floats2bfloat162_rn(v.z, v.w);
    uint2 r;
    r.x = *reinterpret_cast<unsigned*>(&lo);
    r.y = *reinterpret_cast<unsigned*>(&hi);
    return r;
}

// Accumulate sum of squared diffs of 8 bf16 pairs (one uint4 each side).
__device__ __forceinline__ void acc8(const uint4& ua, const uint4& uv, float& s) {
    const unsigned* pa = reinterpret_cast<const unsigned*>(&ua);
    const unsigned* pv = reinterpret_cast<const unsigned*>(&uv);
    #pragma unroll
    for (int k = 0; k < 4; ++k) {
        float2 fa = __bfloat1622float2(*reinterpret_cast<const __nv_bfloat162*>(&pa[k]));
        float2 fv = __bfloat1622float2(*reinterpret_cast<const __nv_bfloat162*>(&pv[k]));
        float d;
        d = fa.x - fv.x; s = fmaf(d, d, s);
        d = fa.y - fv.y; s = fmaf(d, d, s);
    }
}

// K1: fp32 -> bf16 staging. Streaming reads (__ldcs, evict-first so the bf16
// writes own L2); writes land in L2 and stay resident for K2.
__global__ void __launch_bounds__(256)
convert_bf16(const float* __restrict__ in, int n4) {
    const float4* __restrict__ inp = (const float4*)in;
    uint2* __restrict__ outp = (uint2*)g_bf;
    const int gtid = blockIdx.x * 256 + threadIdx.x;
    const int gsz  = gridDim.x * 256;

    if (gsz * 4 == n4) {
        // Exact-fit fast path: 4 independent front-batched float4 loads.
        float4 v0 = __ldcs(&inp[gtid]);
        float4 v1 = __ldcs(&inp[gtid + gsz]);
        float4 v2 = __ldcs(&inp[gtid + 2 * gsz]);
        float4 v3 = __ldcs(&inp[gtid + 3 * gsz]);
        outp[gtid]           = pack_bf(v0);
        outp[gtid + gsz]     = pack_bf(v1);
        outp[gtid + 2 * gsz] = pack_bf(v2);
        outp[gtid + 3 * gsz] = pack_bf(v3);
    } else {
        for (int j = gtid; j < n4; j += gsz)
            outp[j] = pack_bf(__ldcs(&inp[j]));
    }
}

// K2: R7 structure (warp per i, front-batched 12-load chunks) on bf16 rows.
// SM-side traffic halves (384 -> 192 MB) and the whole array is L2-resident.
// Labels stay fp32/exact. Epilogue: __stcg + acq_rel atomic (no CCTL.IVALL
// L1 flush; R5/R7 win), last CTA reduces in fixed order (deterministic).
__global__ void __launch_bounds__(256)
triplet_bf16(const float* __restrict__ label,
             const int*   __restrict__ idx1,
             const int*   __restrict__ idx2,
             float* __restrict__ out,
             int B, int D) {
    const int lane = threadIdx.x & 31;
    const int wid  = threadIdx.x >> 5;
    const int i    = blockIdx.x * 8 + wid;

    __shared__ float wloss[8];
    __shared__ bool  isLast;
    float loss = 0.f;

    {
        // _fix_indices replication (broadcast loads of same address)
        const int r1 = idx1[i];
        const int r2 = idx2[i];
        int a = (i + 1 + (r1 % (B - 1))) % B;
        int b = (i + 1 + (r2 % (B - 1))) % B;
        if (b == a) b = (i + 1 + ((r2 + 1) % (B - 1))) % B;

        // Row = 2048 bf16 = 256 uint4 (8 bf16 per uint4).
        const uint4* __restrict__ A  = (const uint4*)(g_bf + (size_t)i * 2048);
        const uint4* __restrict__ T1 = (const uint4*)(g_bf + (size_t)a * 2048);
        const uint4* __restrict__ T2 = (const uint4*)(g_bf + (size_t)b * 2048);

        float s1 = 0.f, s2 = 0.f;

        // 2 chunks of 12 front-batched 16B loads per warp (R7-proven shape).
        #pragma unroll
        for (int c = 0; c < 2; ++c) {
            const int base = lane + c * 128;
            uint4 av[4], v1[4], v2[4];
            #pragma unroll
            for (int u = 0; u < 4; ++u) av[u] = A[base + u * 32];
            #pragma unroll
            for (int u = 0; u < 4; ++u) v1[u] = T1[base + u * 32];
            #pragma unroll
            for (int u = 0; u < 4; ++u) v2[u] = T2[base + u * 32];
            #pragma unroll
            for (int u = 0; u < 4; ++u) {
                acc8(av[u], v1[u], s1);
                acc8(av[u], v2[u], s2);
            }
        }

        s1 = warp_sum(s1);
        s2 = warp_sum(s2);

        if (lane == 0) {
            const float mu    = (float)136.72353790613718;
            const float sigma = (float)62.34640414043511;

            float li_raw = label[i];
            float la = label[a]; if (a < i) la = (la - mu) / sigma;  // normalized by earlier step
            float lb = label[b]; if (b < i) lb = (lb - mu) / sigma;

            float ld1 = fabsf(li_raw - la);
            float ld2 = fabsf(li_raw - lb);
            bool cond = (ld1 >= ld2);

            float dp = cond ? s2 : s1;    // anchor->near squared distance
            float dn = cond ? s1 : s2;    // anchor->far  squared distance
            float near_l = cond ? lb : la;
            float far_l  = cond ? la : lb;

            float li = (li_raw - mu) / sigma;
            float nl = (near_l - mu) / sigma;  // may be double-normalized — matches reference
            float fl = (far_l  - mu) / sigma;

            float alpha = (li - fl) * (li - fl) - (li - nl) * (li - nl);
            float l = dp - dn + 0.5f * alpha;
            loss = l > 0.f ? l : 0.f;
        }
    }

    if (lane == 0) wloss[wid] = loss;
    __syncthreads();

    if (threadIdx.x == 0) {
        float s = 0.f;
        #pragma unroll
        for (int w = 0; w < 8; w++) s += wloss[w];
        __stcg(&g_block[blockIdx.x], s);   // bypass L1, publish to L2

        unsigned int old;
        asm volatile("atom.acq_rel.gpu.global.add.u32 %0, [%1], %2;"
                     : "=r"(old) : "l"(&g_count), "r"(1u) : "memory");
        isLast = (old == (unsigned int)gridDim.x - 1u);
    }
    __syncthreads();

    if (isLast) {
        const int nb = gridDim.x;
        float s = 0.f;
        for (int j = (int)threadIdx.x; j < nb; j += 256)
            s += __ldcg(&g_block[j]);

        __shared__ float sh[8];
        s = warp_sum(s);
        if (lane == 0) sh[wid] = s;
        __syncthreads();
        if (threadIdx.x == 0) {
            float t = 0.f;
            #pragma unroll
            for (int w = 0; w < 8; w++) t += sh[w];
            out[0] = t;
            g_count = 0;  // reset for next graph replay
        }
    }
}

// fp32 fallback for unexpected shapes (R7 structure, fused epilogue).
__global__ void __launch_bounds__(256)
triplet_fp32(const float* __restrict__ feats,
             const float* __restrict__ label,
             const int*   __restrict__ idx1,
             const int*   __restrict__ idx2,
             float* __restrict__ out,
             int B, int D) {
    const int lane = threadIdx.x & 31;
    const int wid  = threadIdx.x >> 5;
    const int i    = blockIdx.x * 8 + wid;

    __shared__ float wloss[8];
    __shared__ bool  isLast;
    float loss = 0.f;

    if (i < B) {
        const int r1 = idx1[i];
        const int r2 = idx2[i];
        int a = (i + 1 + (r1 % (B - 1))) % B;
        int b = (i + 1 + (r2 % (B - 1))) % B;
        if (b == a) b = (i + 1 + ((r2 + 1) % (B - 1))) % B;

        const float4* A  = (const float4*)(feats + (size_t)i * D);
        const float4* T1 = (const float4*)(feats + (size_t)a * D);
        const float4* T2 = (const float4*)(feats + (size_t)b * D);
        const int n4 = D >> 2;
        float s1 = 0.f, s2 = 0.f;
        for (int j = lane; j < n4; j += 32) {
            float4 av = A[j], v1 = T1[j], v2 = T2[j];
            float d;
            d = av.x - v1.x; s1 = fmaf(d, d, s1);
            d = av.y - v1.y; s1 = fmaf(d, d, s1);
            d = av.z - v1.z; s1 = fmaf(d, d, s1);
            d = av.w - v1.w; s1 = fmaf(d, d, s1);
            d = av.x - v2.x; s2 = fmaf(d, d, s2);
            d = av.y - v2.y; s2 = fmaf(d, d, s2);
            d = av.z - v2.z; s2 = fmaf(d, d, s2);
            d = av.w - v2.w; s2 = fmaf(d, d, s2);
        }
        s1 = warp_sum(s1);
        s2 = warp_sum(s2);
        if (lane == 0) {
            const float mu    = (float)136.72353790613718;
            const float sigma = (float)62.34640414043511;
            float li_raw = label[i];
            float la = label[a]; if (a < i) la = (la - mu) / sigma;
            float lb = label[b]; if (b < i) lb = (lb - mu) / sigma;
            float ld1 = fabsf(li_raw - la);
            float ld2 = fabsf(li_raw - lb);
            bool cond = (ld1 >= ld2);
            float dp = cond ? s2 : s1;
            float dn = cond ? s1 : s2;
            float near_l = cond ? lb : la;
            float far_l  = cond ? la : lb;
            float li = (li_raw - mu) / sigma;
            float nl = (near_l - mu) / sigma;
            float fl = (far_l  - mu) / sigma;
            float alpha = (li - fl) * (li - fl) - (li - nl) * (li - nl);
            float l = dp - dn + 0.5f * alpha;
            loss = l > 0.f ? l : 0.f;
        }
    }

    if (lane == 0) wloss[wid] = loss;
    __syncthreads();

    if (threadIdx.x == 0) {
        float s = 0.f;
        #pragma unroll
        for (int w = 0; w < 8; w++) s += wloss[w];
        __stcg(&g_block[blockIdx.x], s);
        unsigned int old;
        asm volatile("atom.acq_rel.gpu.global.add.u32 %0, [%1], %2;"
                     : "=r"(old) : "l"(&g_count), "r"(1u) : "memory");
        isLast = (old == (unsigned int)gridDim.x - 1u);
    }
    __syncthreads();

    if (isLast) {
        const int nb = gridDim.x;
        float s = 0.f;
        for (int j = (int)threadIdx.x; j < nb; j += 256)
            s += __ldcg(&g_block[j]);
        __shared__ float sh[8];
        s = warp_sum(s);
        if (lane == 0) sh[wid] = s;
        __syncthreads();
        if (threadIdx.x == 0) {
            float t = 0.f;
            #pragma unroll
            for (int w = 0; w < 8; w++) t += sh[w];
            out[0] = t;
            g_count = 0;
        }
    }
}

extern "C" void kernel_launch(void* const* d_in, const int* in_sizes, int n_in,
                              void* d_out, int out_size) {
    const float* feats = (const float*)d_in[0];
    const float* label = (const float*)d_in[1];
    const int*   idx1  = (const int*)d_in[2];
    const int*   idx2  = (const int*)d_in[3];

    const int B = in_sizes[1];
    const int D = in_sizes[0] / B;

    if (B == 16384 && D == 2048) {
        const int n4 = (B * D) / 4;            // 8,388,608 float4
        convert_bf16<<<8192, 256>>>(feats, n4); // 8192*256*4 == n4 exact
        triplet_bf16<<<B / 8, 256>>>(label, idx1, idx2, (float*)d_out, B, D);
    } else {
        const int nblocks = (B + 7) / 8;
        triplet_fp32<<<nblocks, 256>>>(feats, label, idx1, idx2, (float*)d_out, B, D);
    }
}

// round 15
// speedup vs baseline: 1.0006x; 1.0006x over previous
#include <cuda_runtime.h>
#include <cuda_bf16.h>

// bf16 staging copy of feats (64 MB; fits entirely in L2).
__device__ __nv_bfloat16 g_bf[33554432];
// Per-CTA partial sums + completion counter.
__device__ float g_block[65536];
__device__ unsigned int g_count = 0;

__device__ __forceinline__ float warp_sum(float v) {
    #pragma unroll
    for (int off = 16; off > 0; off >>= 1)
        v += __shfl_down_sync(0xFFFFFFFFu, v, off);
    return v;
}

__device__ __forceinline__ uint2 pack_bf(float4 v) {
    __nv_bfloat162 lo = __floats2bfloat162_rn(v.x, v.y);
    __nv_bfloat162 hi = __floats2bfloat162_rn(v.z, v.w);
    uint2 r;
    r.x = *reinterpret_cast<unsigned*>(&lo);
    r.y = *reinterpret_cast<unsigned*>(&hi);
    return r;
}

// Packed accumulate: d = a - v in bf16x2 (1 op, no unpack of inputs),
// unpack the DIFF via exact bit ops (bf16 -> f32 is a 16-bit shift),
// accumulate with packed fma.rn.f32x2 (Blackwell FFMA2).
__device__ __forceinline__ void acc_word(unsigned aw, unsigned vw,
                                         unsigned long long& acc) {
    __nv_bfloat162 a2 = *reinterpret_cast<const __nv_bfloat162*>(&aw);
    __nv_bfloat162 v2 = *reinterpret_cast<const __nv_bfloat162*>(&vw);
    __nv_bfloat162 d2 = __hsub2(a2, v2);
    unsigned du = *reinterpret_cast<unsigned*>(&d2);
    unsigned lo = du << 16;
    unsigned hi = du & 0xffff0000u;
    unsigned long long dd;
    asm("mov.b64 %0, {%1, %2};" : "=l"(dd) : "r"(lo), "r"(hi));
    asm("fma.rn.f32x2 %0, %1, %1, %0;" : "+l"(acc) : "l"(dd));
}

__device__ __forceinline__ float acc_final(unsigned long long acc) {
    unsigned lo, hi;
    asm("mov.b64 {%0, %1}, %2;" : "=r"(lo), "=r"(hi) : "l"(acc));
    return __uint_as_float(lo) + __uint_as_float(hi);
}

// K1: fp32 -> bf16 staging. __ldcs reads (evict-first) so the bf16 writes own L2.
__global__ void __launch_bounds__(256)
convert_bf16(const float* __restrict__ in, int n4) {
    const float4* __restrict__ inp = (const float4*)in;
    uint2* __restrict__ outp = (uint2*)g_bf;
    const int gtid = blockIdx.x * 256 + threadIdx.x;
    const int gsz  = gridDim.x * 256;

    if (gsz * 4 == n4) {
        float4 v0 = __ldcs(&inp[gtid]);
        float4 v1 = __ldcs(&inp[gtid + gsz]);
        float4 v2 = __ldcs(&inp[gtid + 2 * gsz]);
        float4 v3 = __ldcs(&inp[gtid + 3 * gsz]);
        outp[gtid]           = pack_bf(v0);
        outp[gtid + gsz]     = pack_bf(v1);
        outp[gtid + 2 * gsz] = pack_bf(v2);
        outp[gtid + 3 * gsz] = pack_bf(v3);
    } else {
        for (int j = gtid; j < n4; j += gsz)
            outp[j] = pack_bf(__ldcs(&inp[j]));
    }
}

// K2: warp per i (R7 shape) on bf16 rows with packed hsub2/ffma2 inner loop.
// R14 showed this kernel issue-bound (50.3%) at 14 ops/word; this cuts to ~8.
// Labels fp32/exact. Epilogue: __stcg + acq_rel atomic (no CCTL.IVALL; R5/R7),
// last CTA reduces in fixed order (deterministic).
__global__ void __launch_bounds__(256)
triplet_bf16(const float* __restrict__ label,
             const int*   __restrict__ idx1,
             const int*   __restrict__ idx2,
             float* __restrict__ out,
             int B, int D) {
    const int lane = threadIdx.x & 31;
    const int wid  = threadIdx.x >> 5;
    const int i    = blockIdx.x * 8 + wid;

    __shared__ float wloss[8];
    __shared__ bool  isLast;
    float loss = 0.f;

    {
        const int r1 = idx1[i];
        const int r2 = idx2[i];
        int a = (i + 1 + (r1 % (B - 1))) % B;
        int b = (i + 1 + (r2 % (B - 1))) % B;
        if (b == a) b = (i + 1 + ((r2 + 1) % (B - 1))) % B;

        // Row = 2048 bf16 = 256 uint4.
        const uint4* __restrict__ A  = (const uint4*)(g_bf + (size_t)i * 2048);
        const uint4* __restrict__ T1 = (const uint4*)(g_bf + (size_t)a * 2048);
        const uint4* __restrict__ T2 = (const uint4*)(g_bf + (size_t)b * 2048);

        unsigned long long acc1 = 0ull, acc2 = 0ull;

        // 2 chunks of 12 front-batched 16B loads per warp (R7-proven shape).
        #pragma unroll
        for (int c = 0; c < 2; ++c) {
            const int base = lane + c * 128;
            uint4 av[4], v1[4], v2[4];
            #pragma unroll
            for (int u = 0; u < 4; ++u) av[u] = A[base + u * 32];
            #pragma unroll
            for (int u = 0; u < 4; ++u) v1[u] = T1[base + u * 32];
            #pragma unroll
            for (int u = 0; u < 4; ++u) v2[u] = T2[base + u * 32];
            #pragma unroll
            for (int u = 0; u < 4; ++u) {
                acc_word(av[u].x, v1[u].x, acc1);
                acc_word(av[u].y, v1[u].y, acc1);
                acc_word(av[u].z, v1[u].z, acc1);
                acc_word(av[u].w, v1[u].w, acc1);
                acc_word(av[u].x, v2[u].x, acc2);
                acc_word(av[u].y, v2[u].y, acc2);
                acc_word(av[u].z, v2[u].z, acc2);
                acc_word(av[u].w, v2[u].w, acc2);
            }
        }

        float s1 = warp_sum(acc_final(acc1));
        float s2 = warp_sum(acc_final(acc2));

        if (lane == 0) {
            const float mu    = (float)136.72353790613718;
            const float sigma = (float)62.34640414043511;

            float li_raw = label[i];
            float la = label[a]; if (a < i) la = (la - mu) / sigma;  // normalized by earlier step
            float lb = label[b]; if (b < i) lb = (lb - mu) / sigma;

            float ld1 = fabsf(li_raw - la);
            float ld2 = fabsf(li_raw - lb);
            bool cond = (ld1 >= ld2);

            float dp = cond ? s2 : s1;    // anchor->near squared distance
            float dn = cond ? s1 : s2;    // anchor->far  squared distance
            float near_l = cond ? lb : la;
            float far_l  = cond ? la : lb;

            float li = (li_raw - mu) / sigma;
            float nl = (near_l - mu) / sigma;  // may be double-normalized — matches reference
            float fl = (far_l  - mu) / sigma;

            float alpha = (li - fl) * (li - fl) - (li - nl) * (li - nl);
            float l = dp - dn + 0.5f * alpha;
            loss = l > 0.f ? l : 0.f;
        }
    }

    if (lane == 0) wloss[wid] = loss;
    __syncthreads();

    if (threadIdx.x == 0) {
        float s = 0.f;
        #pragma unroll
        for (int w = 0; w < 8; w++) s += wloss[w];
        __stcg(&g_block[blockIdx.x], s);   // bypass L1, publish to L2

        unsigned int old;
        asm volatile("atom.acq_rel.gpu.global.add.u32 %0, [%1], %2;"
                     : "=r"(old) : "l"(&g_count), "r"(1u) : "memory");
        isLast = (old == (unsigned int)gridDim.x - 1u);
    }
    __syncthreads();

    if (isLast) {
        const int nb = gridDim.x;
        float s = 0.f;
        for (int j = (int)threadIdx.x; j < nb; j += 256)
            s += __ldcg(&g_block[j]);

        __shared__ float sh[8];
        s = warp_sum(s);
        if (lane == 0) sh[wid] = s;
        __syncthreads();
        if (threadIdx.x == 0) {
            float t = 0.f;
            #pragma unroll
            for (int w = 0; w < 8; w++) t += sh[w];
            out[0] = t;
            g_count = 0;  // reset for next graph replay
        }
    }
}

// fp32 fallback for unexpected shapes (R7 structure, fused epilogue).
__global__ void __launch_bounds__(256)
triplet_fp32(const float* __restrict__ feats,
             const float* __restrict__ label,
             const int*   __restrict__ idx1,
             const int*   __restrict__ idx2,
             float* __restrict__ out,
             int B, int D) {
    const int lane = threadIdx.x & 31;
    const int wid  = threadIdx.x >> 5;
    const int i    = blockIdx.x * 8 + wid;

    __shared__ float wloss[8];
    __shared__ bool  isLast;
    float loss = 0.f;

    if (i < B) {
        const int r1 = idx1[i];
        const int r2 = idx2[i];
        int a = (i + 1 + (r1 % (B - 1))) % B;
        int b = (i + 1 + (r2 % (B - 1))) % B;
        if (b == a) b = (i + 1 + ((r2 + 1) % (B - 1))) % B;

        const float4* A  = (const float4*)(feats + (size_t)i * D);
        const float4* T1 = (const float4*)(feats + (size_t)a * D);
        const float4* T2 = (const float4*)(feats + (size_t)b * D);
        const int n4 = D >> 2;
        float s1 = 0.f, s2 = 0.f;
        for (int j = lane; j < n4; j += 32) {
            float4 av = A[j], v1 = T1[j], v2 = T2[j];
            float d;
            d = av.x - v1.x; s1 = fmaf(d, d, s1);
            d = av.y - v1.y; s1 = fmaf(d, d, s1);
            d = av.z - v1.z; s1 = fmaf(d, d, s1);
            d = av.w - v1.w; s1 = fmaf(d, d, s1);
            d = av.x - v2.x; s2 = fmaf(d, d, s2);
            d = av.y - v2.y; s2 = fmaf(d, d, s2);
            d = av.z - v2.z; s2 = fmaf(d, d, s2);
            d = av.w - v2.w; s2 = fmaf(d, d, s2);
        }
        s1 = warp_sum(s1);
        s2 = warp_sum(s2);
        if (lane == 0) {
            const float mu    = (float)136.72353790613718;
            const float sigma = (float)62.34640414043511;
            float li_raw = label[i];
            float la = label[a]; if (a < i) la = (la - mu) / sigma;
            float lb = label[b]; if (b < i) lb = (lb - mu) / sigma;
            float ld1 = fabsf(li_raw - la);
            float ld2 = fabsf(li_raw - lb);
            bool cond = (ld1 >= ld2);
            float dp = cond ? s2 : s1;
            float dn = cond ? s1 : s2;
            float near_l = cond ? lb : la;
            float far_l  = cond ? la : lb;
            float li = (li_raw - mu) / sigma;
            float nl = (near_l - mu) / sigma;
            float fl = (far_l  - mu) / sigma;
            float alpha = (li - fl) * (li - fl) - (li - nl) * (li - nl);
            float l = dp - dn + 0.5f * alpha;
            loss = l > 0.f ? l : 0.f;
        }
    }

    if (lane == 0) wloss[wid] = loss;
    __syncthreads();

    if (threadIdx.x == 0) {
        float s = 0.f;
        #pragma unroll
        for (int w = 0; w < 8; w++) s += wloss[w];
        __stcg(&g_block[blockIdx.x], s);
        unsigned int old;
        asm volatile("atom.acq_rel.gpu.global.add.u32 %0, [%1], %2;"
                     : "=r"(old) : "l"(&g_count), "r"(1u) : "memory");
        isLast = (old == (unsigned int)gridDim.x - 1u);
    }
    __syncthreads();

    if (isLast) {
        const int nb = gridDim.x;
        float s = 0.f;
        for (int j = (int)threadIdx.x; j < nb; j += 256)
            s += __ldcg(&g_block[j]);
        __shared__ float sh[8];
        s = warp_sum(s);
        if (lane == 0) sh[wid] = s;
        __syncthreads();
        if (threadIdx.x == 0) {
            float t = 0.f;
            #pragma unroll
            for (int w = 0; w < 8; w++) t += sh[w];
            out[0] = t;
            g_count = 0;
        }
    }
}

extern "C" void kernel_launch(void* const* d_in, const int* in_sizes, int n_in,
                              void* d_out, int out_size) {
    const float* feats = (const float*)d_in[0];
    const float* label = (const float*)d_in[1];
    const int*   idx1  = (const int*)d_in[2];
    const int*   idx2  = (const int*)d_in[3];

    const int B = in_sizes[1];
    const int D = in_sizes[0] / B;

    if (B == 16384 && D == 2048) {
        const int n4 = (B * D) / 4;             // 8,388,608 float4
        convert_bf16<<<8192, 256>>>(feats, n4);  // 8192*256*4 == n4 exact
        triplet_bf16<<<B / 8, 256>>>(label, idx1, idx2, (float*)d_out, B, D);
    } else {
        const int nblocks = (B + 7) / 8;
        triplet_fp32<<<nblocks, 256>>>(feats, label, idx1, idx2, (float*)d_out, B, D);
    }
}

// round 16
// speedup vs baseline: 1.1902x; 1.1895x over previous
#include <cuda_runtime.h>

// Per-CTA partial sums + completion counter. 16384/8 = 2048 CTAs for this problem.
__device__ float g_block[65536];
__device__ unsigned int g_count = 0;

__device__ __forceinline__ float warp_sum(float v) {
    #pragma unroll
    for (int off = 16; off > 0; off >>= 1)
        v += __shfl_down_sync(0xFFFFFFFFu, v, off);
    return v;
}

// CHAMPION (R7 config, 43.0us measured). One warp per i, 8 warps per CTA.
// Each warp: 4 chunks of 12 front-batched float4 loads (MLP=12); warp-shuffle
// reduce; lane 0 computes loss_i. CTA sums 8 losses into g_block[bid]; last
// CTA reduces all partials in fixed order (deterministic). Proven wins kept:
//  - __ldcs anchors (evict-first streaming; -33MB DRAM, R7)
//  - acq_rel atomic completion, NOT __threadfence (gpu-scope fence emits
//    CCTL.IVALL = full L1D flush; cost ~5us, R5)
//  - __stcg partials (publish straight to L2), __ldcg final reduce (L2-hot)
// Falsified alternatives (R8-R15): higher occupancy, 4-warps-per-i, smem
// cp.async pipeline, deep in-register pipeline, L2 evict_last on gathers,
// bf16 staging — all land >= 43us; kernel is LTS-throughput-capped at
// 384 MB SM-side traffic (3 compulsory row-reads x 128 MB).
__global__ void __launch_bounds__(256)
triplet_fused(const float* __restrict__ feats,
              const float* __restrict__ label,
              const int*   __restrict__ idx1,
              const int*   __restrict__ idx2,
              float* __restrict__ out,
              int B, int D) {
    const int lane = threadIdx.x & 31;
    const int wid  = threadIdx.x >> 5;
    const int i    = blockIdx.x * 8 + wid;

    __shared__ float wloss[8];
    __shared__ bool  isLast;
    float loss = 0.f;

    if (i < B) {
        // _fix_indices replication (broadcast loads of same address)
        const int r1 = idx1[i];
        const int r2 = idx2[i];
        int a = (i + 1 + (r1 % (B - 1))) % B;
        int b = (i + 1 + (r2 % (B - 1))) % B;
        if (b == a) b = (i + 1 + ((r2 + 1) % (B - 1))) % B;

        const float4* __restrict__ A  = (const float4*)(feats + (size_t)i * D);
        const float4* __restrict__ T1 = (const float4*)(feats + (size_t)a * D);
        const float4* __restrict__ T2 = (const float4*)(feats + (size_t)b * D);

        const int n4 = D >> 2;   // 512 for D=2048
        float s1 = 0.f, s2 = 0.f;

        if ((n4 & 127) == 0) {
            // Chunks of 4 j-steps per warp: 12 front-batched float4 loads.
            // Anchor via __ldcs (evict-first): streamed once sequentially,
            // leaves L2 room for the random gather working set.
            const int nchunk = n4 >> 7;          // 4 for D=2048
            for (int c = 0; c < nchunk; ++c) {
                const int base = lane + c * 128;
                float4 av[4], v1[4], v2[4];
                #pragma unroll
                for (int u = 0; u < 4; ++u) av[u] = __ldcs(&A[base + u * 32]);
                #pragma unroll
                for (int u = 0; u < 4; ++u) v1[u] = T1[base + u * 32];
                #pragma unroll
                for (int u = 0; u < 4; ++u) v2[u] = T2[base + u * 32];
                #pragma unroll
                for (int u = 0; u < 4; ++u) {
                    float d;
                    d = av[u].x - v1[u].x; s1 = fmaf(d, d, s1);
                    d = av[u].y - v1[u].y; s1 = fmaf(d, d, s1);
                    d = av[u].z - v1[u].z; s1 = fmaf(d, d, s1);
                    d = av[u].w - v1[u].w; s1 = fmaf(d, d, s1);
                    d = av[u].x - v2[u].x; s2 = fmaf(d, d, s2);
                    d = av[u].y - v2[u].y; s2 = fmaf(d, d, s2);
                    d = av[u].z - v2[u].z; s2 = fmaf(d, d, s2);
                    d = av[u].w - v2[u].w; s2 = fmaf(d, d, s2);
                }
            }
        } else {
            for (int j = lane; j < n4; j += 32) {
                float4 av = A[j];
                float4 v1 = T1[j];
                float4 v2 = T2[j];
                float d;
                d = av.x - v1.x; s1 = fmaf(d, d, s1);
                d = av.y - v1.y; s1 = fmaf(d, d, s1);
                d = av.z - v1.z; s1 = fmaf(d, d, s1);
                d = av.w - v1.w; s1 = fmaf(d, d, s1);
                d = av.x - v2.x; s2 = fmaf(d, d, s2);
                d = av.y - v2.y; s2 = fmaf(d, d, s2);
                d = av.z - v2.z; s2 = fmaf(d, d, s2);
                d = av.w - v2.w; s2 = fmaf(d, d, s2);
            }
        }

        s1 = warp_sum(s1);
        s2 = warp_sum(s2);

        if (lane == 0) {
            const float mu    = (float)136.72353790613718;
            const float sigma = (float)62.34640414043511;

            float li_raw = label[i];
            float la = label[a]; if (a < i) la = (la - mu) / sigma;  // normalized by earlier step
            float lb = label[b]; if (b < i) lb = (lb - mu) / sigma;

            float ld1 = fabsf(li_raw - la);
            float ld2 = fabsf(li_raw - lb);
            bool cond = (ld1 >= ld2);

            float dp = cond ? s2 : s1;    // anchor->near squared distance
            float dn = cond ? s1 : s2;    // anchor->far  squared distance
            float near_l = cond ? lb : la;
            float far_l  = cond ? la : lb;

            float li = (li_raw - mu) / sigma;
            float nl = (near_l - mu) / sigma;  // may be double-normalized — matches reference
            float fl = (far_l  - mu) / sigma;

            float alpha = (li - fl) * (li - fl) - (li - nl) * (li - nl);
            float l = dp - dn + 0.5f * alpha;
            loss = l > 0.f ? l : 0.f;
        }
    }

    if (lane == 0) wloss[wid] = loss;
    __syncthreads();

    if (threadIdx.x == 0) {
        float s = 0.f;
        #pragma unroll
        for (int w = 0; w < 8; w++) s += wloss[w];
        __stcg(&g_block[blockIdx.x], s);   // bypass L1, publish to L2

        // acq_rel atomic: releases the __stcg above, acquires for the
        // __ldcg reads below. No CCTL.IVALL (unlike __threadfence).
        unsigned int old;
        asm volatile("atom.acq_rel.gpu.global.add.u32 %0, [%1], %2;"
                     : "=r"(old) : "l"(&g_count), "r"(1u) : "memory");
        isLast = (old == (unsigned int)gridDim.x - 1u);
    }
    __syncthreads();

    if (isLast) {
        // Partials are L2-hot (just written via __stcg). Fixed order.
        const int nb = gridDim.x;
        float s = 0.f;
        for (int j = (int)threadIdx.x; j < nb; j += 256)
            s += __ldcg(&g_block[j]);

        __shared__ float sh[8];
        s = warp_sum(s);
        if (lane == 0) sh[wid] = s;
        __syncthreads();
        if (threadIdx.x == 0) {
            float t = 0.f;
            #pragma unroll
            for (int w = 0; w < 8; w++) t += sh[w];
            out[0] = t;
            g_count = 0;  // reset for next graph replay
        }
    }
}

extern "C" void kernel_launch(void* const* d_in, const int* in_sizes, int n_in,
                              void* d_out, int out_size) {
    const float* feats = (const float*)d_in[0];
    const float* label = (const float*)d_in[1];
    const int*   idx1  = (const int*)d_in[2];
    const int*   idx2  = (const int*)d_in[3];

    const int B = in_sizes[1];
    const int D = in_sizes[0] / B;
    const int nblocks = (B + 7) / 8;

    triplet_fused<<<nblocks, 256>>>(feats, label, idx1, idx2, (float*)d_out, B, D);
}